// round 16
// baseline (speedup 1.0000x reference)
#include <cuda_runtime.h>
#include <cuda_fp16.h>
#include <cstdint>
#include <math.h>

#define TCONST 512
#define LSEQ   1616
#define MLEN   1536
#define CDIM   768
#define NHEAD  12
#define HD     64
#define BMAX   8

// fp16 scratch — all operands single fp16.
__device__ __half g_xh[BMAX * LSEQ * CDIM];
__device__ __half g_wh[4 * CDIM * CDIM];
__device__ __half g_qh[BMAX * NHEAD * LSEQ * HD];
__device__ __half g_kh[BMAX * NHEAD * LSEQ * HD];
__device__ __half g_vh[BMAX * NHEAD * LSEQ * HD];
__device__ __half g_yh[BMAX * LSEQ * CDIM];

// heavy-first q-tile schedule (descending visited-tile count)
__device__ const unsigned char QT_ORDER[26] = {
    23, 22, 21, 15, 20, 14, 19, 13, 12, 18, 11, 17, 10,
    7, 6, 9, 5, 16, 4, 8, 3, 2, 24, 25, 1, 0
};

// ---------------------------------------------------------------------------
__device__ __forceinline__ uint32_t smem_u32(const void* p) {
    uint32_t a;
    asm("{ .reg .u64 t; cvta.to.shared.u64 t, %1; cvt.u32.u64 %0, t; }"
        : "=r"(a) : "l"(p));
    return a;
}

#define LDSM4(r, addr) asm volatile( \
    "ldmatrix.sync.aligned.m8n8.x4.shared.b16 {%0,%1,%2,%3}, [%4];" \
    : "=r"((r)[0]), "=r"((r)[1]), "=r"((r)[2]), "=r"((r)[3]) : "r"(addr))

#define LDSM4T(r, addr) asm volatile( \
    "ldmatrix.sync.aligned.m8n8.x4.trans.shared.b16 {%0,%1,%2,%3}, [%4];" \
    : "=r"((r)[0]), "=r"((r)[1]), "=r"((r)[2]), "=r"((r)[3]) : "r"(addr))

#define MMA16816(c, a, b) asm volatile( \
    "mma.sync.aligned.m16n8k16.row.col.f32.f16.f16.f32 " \
    "{%0,%1,%2,%3}, {%4,%5,%6,%7}, {%8,%9}, {%0,%1,%2,%3};" \
    : "+f"((c)[0]), "+f"((c)[1]), "+f"((c)[2]), "+f"((c)[3]) \
    : "r"((a)[0]), "r"((a)[1]), "r"((a)[2]), "r"((a)[3]), "r"((b)[0]), "r"((b)[1]))

#define CPA16(dst, src, sz) asm volatile( \
    "cp.async.ca.shared.global [%0], [%1], 16, %2;" \
    :: "r"(dst), "l"(src), "r"(sz) : "memory")
#define CPA_COMMIT() asm volatile("cp.async.commit_group;" ::: "memory")
#define CPA_WAIT(n)  asm volatile("cp.async.wait_group %0;" :: "n"(n) : "memory")

#define EX2F(d, s) asm("ex2.approx.f32 %0, %1;" : "=f"(d) : "f"(s))

// ---------------------------------------------------------------------------
// Pre-convert kernels
// ---------------------------------------------------------------------------
__global__ void __launch_bounds__(256) split_x(const float* __restrict__ s, int n)
{
    int i = (blockIdx.x * 256 + threadIdx.x) * 4;
    if (i >= n) return;
    float4 v = *(const float4*)(s + i);
    __half2 a = __floats2half2_rn(v.x, v.y);
    __half2 b = __floats2half2_rn(v.z, v.w);
    *(uint2*)(g_xh + i) = make_uint2(*reinterpret_cast<uint32_t*>(&a),
                                     *reinterpret_cast<uint32_t*>(&b));
}

__global__ void __launch_bounds__(256) split_w(
    const float* __restrict__ wq, const float* __restrict__ wk,
    const float* __restrict__ wv, const float* __restrict__ wp)
{
    int z = blockIdx.z;
    const float* s = (z == 0) ? wq : (z == 1) ? wk : (z == 2) ? wv : wp;
    int i = (blockIdx.x * 256 + threadIdx.x) * 4;
    float4 v = *(const float4*)(s + i);
    __half2 a = __floats2half2_rn(v.x, v.y);
    __half2 b = __floats2half2_rn(v.z, v.w);
    size_t o = (size_t)z * CDIM * CDIM + i;
    *(uint2*)(g_wh + o) = make_uint2(*reinterpret_cast<uint32_t*>(&a),
                                     *reinterpret_cast<uint32_t*>(&b));
}

// ---------------------------------------------------------------------------
// HMMA GEMM fp16: O = A * W^T + bias.
// 128x128 tile/CTA; 8 warps as 4x2, warp tile 32x64, 1 MMA per pair.
// ---------------------------------------------------------------------------
#define ROWB   80
#define TILEB  (128 * ROWB)
#define GBUF   (2 * TILEB)          // A, B
#define GSMEM  (2 * GBUF)           // double-buffered = 40960

template <int MODE>
__device__ __forceinline__ void hmma_gemm_body(
    const __half* __restrict__ Ah, const __half* __restrict__ Bh,
    const float* __restrict__ bias, float oscale,
    float* __restrict__ O, __half* __restrict__ Ohi, int M)
{
    extern __shared__ char sm[];
    const uint32_t sb = smem_u32(sm);

    const int tid  = threadIdx.x;
    const int lane = tid & 31;
    const int wid  = tid >> 5;
    const int mBase = blockIdx.y * 128;
    const int nBase = blockIdx.x * 128;
    const int wm = (wid & 3) * 32;
    const int wn = (wid >> 2) * 64;

    const int a_row  = ((lane >> 3) & 1) * 8 + (lane & 7);
    const int a_koff = (lane >> 4) * 16;
    const int b_row  = ((lane >> 4) & 1) * 8 + (lane & 7);
    const int b_koff = ((lane >> 3) & 1) * 16;

    const int r_st  = tid >> 1;
    const int sg_st = (tid & 1) * 32;
    const int  arow = mBase + r_st;
    const bool aval = arow < M;
    const char* ArH = (const char*)(Ah + (size_t)(aval ? arow : 0) * CDIM);
    const char* BrH = (const char*)(Bh + (size_t)(nBase + r_st) * CDIM);
    const uint32_t smoff = (uint32_t)r_st * ROWB + sg_st;
    const int asz = aval ? 16 : 0;

    float acc[2][8][4];
#pragma unroll
    for (int i = 0; i < 2; i++)
#pragma unroll
        for (int j = 0; j < 8; j++)
#pragma unroll
            for (int r = 0; r < 4; r++) acc[i][j][r] = 0.f;

    const int NC = CDIM / 32;   // 24

    {
        uint32_t d = sb + smoff;
        int gb = sg_st;
        CPA16(d, ArH + gb, asz);           CPA16(d + 16, ArH + gb + 16, asz);
        CPA16(d + TILEB, BrH + gb, 16);    CPA16(d + TILEB + 16, BrH + gb + 16, 16);
        CPA_COMMIT();
    }

    for (int c = 0; c < NC; c++) {
        if (c + 1 < NC) {
            uint32_t d = sb + (uint32_t)((c + 1) & 1) * GBUF + smoff;
            int gb = (c + 1) * 64 + sg_st;
            CPA16(d, ArH + gb, asz);           CPA16(d + 16, ArH + gb + 16, asz);
            CPA16(d + TILEB, BrH + gb, 16);    CPA16(d + TILEB + 16, BrH + gb + 16, 16);
            CPA_COMMIT();
            CPA_WAIT(1);
        } else {
            CPA_WAIT(0);
        }
        __syncthreads();

        const uint32_t bufA = sb + (uint32_t)(c & 1) * GBUF;
        const uint32_t bufB = bufA + TILEB;
#pragma unroll
        for (int ks = 0; ks < 2; ks++) {
            uint32_t ah[2][4];
#pragma unroll
            for (int mt = 0; mt < 2; mt++) {
                uint32_t addr = bufA + (uint32_t)(wm + mt * 16 + a_row) * ROWB
                              + ks * 32 + a_koff;
                LDSM4(ah[mt], addr);
            }
            uint32_t bh[8][2];
#pragma unroll
            for (int np = 0; np < 4; np++) {
                uint32_t addr = bufB + (uint32_t)(wn + np * 16 + b_row) * ROWB
                              + ks * 32 + b_koff;
                uint32_t t[4];
                LDSM4(t, addr);
                bh[np * 2][0] = t[0]; bh[np * 2][1] = t[1];
                bh[np * 2 + 1][0] = t[2]; bh[np * 2 + 1][1] = t[3];
            }
#pragma unroll
            for (int mt = 0; mt < 2; mt++)
#pragma unroll
                for (int nt = 0; nt < 8; nt++)
                    MMA16816(acc[mt][nt], ah[mt], bh[nt]);
        }
        __syncthreads();
    }

#pragma unroll
    for (int mt = 0; mt < 2; mt++) {
#pragma unroll
        for (int nt = 0; nt < 8; nt++) {
            int cc = nBase + wn + nt * 8 + (lane & 3) * 2;
            float bx = bias[cc], by = bias[cc + 1];
#pragma unroll
            for (int half = 0; half < 2; half++) {
                int m = mBase + wm + mt * 16 + (lane >> 2) + half * 8;
                if (m >= M) continue;
                float vx = (acc[mt][nt][half * 2] + bx) * oscale;
                float vy = (acc[mt][nt][half * 2 + 1] + by) * oscale;
                if (MODE == 0) {
                    int b = m / LSEQ, l = m % LSEQ;
                    int h = cc >> 6, d = cc & 63;
                    size_t off = (((size_t)b * NHEAD + h) * LSEQ + l) * HD + d;
                    __half2 hv = __floats2half2_rn(vx, vy);
                    *(uint32_t*)(Ohi + off) = *reinterpret_cast<uint32_t*>(&hv);
                } else {
                    *(float2*)(O + (size_t)m * CDIM + cc) = make_float2(vx, vy);
                }
            }
        }
    }
}

__global__ void __launch_bounds__(256, 2) gemm_qkv(
    const float* __restrict__ bq, const float* __restrict__ bk,
    const float* __restrict__ bv, int M)
{
    int z = blockIdx.z;
    const float* bs = (z == 0) ? bq : ((z == 1) ? bk : bv);
    __half* Oh = (z == 0) ? g_qh : ((z == 1) ? g_kh : g_vh);
    // q carries 1/sqrt(64) AND log2(e) so flash can use exp2 directly
    float sc = (z == 0) ? 0.125f * 1.44269504f : 1.0f;
    hmma_gemm_body<0>(g_xh, g_wh + (size_t)z * CDIM * CDIM, bs, sc,
                      nullptr, Oh, M);
}

__global__ void __launch_bounds__(256, 2) gemm_proj(
    const float* __restrict__ bp, float* __restrict__ out, int M)
{
    hmma_gemm_body<1>(g_yh, g_wh + (size_t)3 * CDIM * CDIM, bp, 1.0f,
                      out, nullptr, M);
}

// ---------------------------------------------------------------------------
// Mask helpers
// ---------------------------------------------------------------------------
__device__ __forceinline__ bool blocked_qk(int q, int k)
{
    if (q >= MLEN) return k < MLEN;
    if (k >= MLEN) return q < TCONST;
    int qb = q >> 9, kb = k >> 9;
    int qi = q & 511, ki = k & 511;
    if (qb == 0) return !(kb == 0 && qi >= ki);
    if (qb == 1) return (kb == 0) ? (qi < ki) : (qi <= ki);
    return (kb == 2) ? (qi <= ki) : (qi < ki);
}

__device__ __forceinline__ bool tile_visit(int qt, int kt)
{
    bool qtext = (qt >= 24), ktext = (kt >= 24);
    if (qtext) return ktext;
    if (ktext) return qt >= 8;
    return ((qt & 7) >= (kt & 7)) && !((qt < 8) && (kt >= 8));
}
__device__ __forceinline__ bool tile_partial(int qt, int kt)
{
    if (kt == 25) return true;
    return (qt < 24) && (kt < 24) && ((qt & 7) == (kt & 7));
}

// ---------------------------------------------------------------------------
// HMMA flash attention v8 (fp16 single operands, log2-domain softmax):
// 128-key tiles processed as two 64-key halves (per-half skip flags),
// p = ex2(s') with s' pre-scaled by log2e (no stabilizer; constant cancels).
// CTA = 64 q-rows, 4 warps, 4 CTAs/SM. smem = K|V 128-row tiles = 36.9 KB.
// ---------------------------------------------------------------------------
#define FROWB  144
#define FHALF  (64 * FROWB)              // 9216 B (one 64-row half)
#define FKTILE (128 * FROWB)             // 18432 B
#define FSMEM  (2 * FKTILE)              // 36864 B (K, V)

__global__ void __launch_bounds__(128, 4) flash_attn_mma(int B)
{
    extern __shared__ char smx[];
    const uint32_t sb = smem_u32(smx);

    const int bh = blockIdx.y;
    const int b  = bh / NHEAD, h = bh % NHEAD;
    const int qt = QT_ORDER[blockIdx.x];       // heavy tiles first
    const int q0 = qt * 64;

    const size_t base = ((size_t)b * NHEAD + h) * LSEQ * HD;
    const char* src2[2] = { (const char*)(g_kh + base),
                            (const char*)(g_vh + base) };
    const __half* Qh = g_qh + base;

    const int tid  = threadIdx.x;
    const int lane = tid & 31;
    const int qr   = (lane & 3) * 2;
    const int g    = lane >> 2;

    const int b_row  = ((lane >> 4) & 1) * 8 + (lane & 7);
    const int b_koff = ((lane >> 3) & 1) * 16;

    const int qrow0 = q0 + (tid >> 5) * 16 + g;
    const int qrow1 = qrow0 + 8;

    // ---- 128-key pair list with per-half flags (0=skip,1=full,2=partial) ----
    uint32_t list[13];
    int nv = 0;
    for (int p = 0; p < 13; p++) {
        int f0 = 0, f1 = 0;
        if (tile_visit(qt, 2 * p))     f0 = tile_partial(qt, 2 * p) ? 2 : 1;
        if (tile_visit(qt, 2 * p + 1)) f1 = tile_partial(qt, 2 * p + 1) ? 2 : 1;
        if (f0 | f1) list[nv++] = (uint32_t)p | (f0 << 8) | (f1 << 12);
    }

    // Q fragments (pre-scaled by log2e/8 in gemm; single fp16)
    uint32_t qh[4][4];
#pragma unroll
    for (int ks = 0; ks < 4; ks++) {
#pragma unroll
        for (int part = 0; part < 4; part++) {
            int row = (part & 1) ? qrow1 : qrow0;
            int col = ks * 16 + qr + (part >> 1) * 8;
            qh[ks][part] = (row < LSEQ)
                ? *(const uint32_t*)(Qh + (size_t)row * HD + col) : 0;
        }
    }

    float oacc[8][4];
#pragma unroll
    for (int i = 0; i < 8; i++)
#pragma unroll
        for (int r = 0; r < 4; r++) oacc[i][r] = 0.f;
    float l0 = 0.f, l1 = 0.f;

    const int rr  = tid >> 3;               // 0..15
    const int seg = (tid & 7) * 16;

    for (int i = 0; i < nv; i++) {
        const int p  = list[i] & 0xff;
        const int k0 = p * 128;

        // ---- load 128-row K and V tiles ----
        __syncthreads();
#pragma unroll
        for (int t = 0; t < 2; t++) {
#pragma unroll
            for (int j = 0; j < 8; j++) {
                int r = rr + j * 16;        // 0..127
                int row = k0 + r;
                bool ok = row < LSEQ;
                const char* gp = src2[t] + (size_t)(ok ? row : 0) * (HD * 2) + seg;
                uint32_t d = sb + t * FKTILE + (uint32_t)r * FROWB + seg;
                CPA16(d, gp, ok ? 16 : 0);
            }
        }
        CPA_COMMIT();
        CPA_WAIT(0);
        __syncthreads();

#pragma unroll
        for (int half = 0; half < 2; half++) {
            const int f = (list[i] >> (8 + half * 4)) & 3;
            if (!f) continue;
            const int k0h = k0 + half * 64;
            const uint32_t khi = sb + (uint32_t)half * FHALF;
            const uint32_t vhi = sb + FKTILE + (uint32_t)half * FHALF;

            // ---- S' = Q K^T (already in log2 domain) ----
            float sacc[8][4];
#pragma unroll
            for (int ii = 0; ii < 8; ii++)
#pragma unroll
                for (int r = 0; r < 4; r++) sacc[ii][r] = 0.f;
#pragma unroll
            for (int ks = 0; ks < 4; ks++) {
#pragma unroll
                for (int kg = 0; kg < 4; kg++) {
                    uint32_t addr = khi + (uint32_t)(kg * 16 + b_row) * FROWB
                                  + ks * 32 + b_koff;
                    uint32_t th[4];
                    LDSM4(th, addr);
                    uint32_t bh0[2] = {th[0], th[1]}, bh1[2] = {th[2], th[3]};
                    MMA16816(sacc[kg * 2],     qh[ks], bh0);
                    MMA16816(sacc[kg * 2 + 1], qh[ks], bh1);
                }
            }

            if (f == 2) {
#pragma unroll
                for (int nt = 0; nt < 8; nt++) {
                    int kc = k0h + nt * 8 + qr;
#pragma unroll
                    for (int e = 0; e < 2; e++) {
                        int kk = kc + e;
                        bool kb = (kk >= LSEQ);
                        if (kb || qrow0 >= LSEQ || blocked_qk(qrow0, kk))
                            sacc[nt][e] = -1e30f;
                        if (kb || qrow1 >= LSEQ || blocked_qk(qrow1, kk))
                            sacc[nt][2 + e] = -1e30f;
                    }
                }
            }

            // ---- p = 2^s', fp16-quantized consistently for num/denom ----
            uint32_t ph[4][4];
#pragma unroll
            for (int nt = 0; nt < 8; nt++) {
                float p0, p1, p2, p3;
                EX2F(p0, sacc[nt][0]);
                EX2F(p1, sacc[nt][1]);
                EX2F(p2, sacc[nt][2]);
                EX2F(p3, sacc[nt][3]);
                __half2 h01 = __floats2half2_rn(p0, p1);
                __half2 h23 = __floats2half2_rn(p2, p3);
                float2 f01 = __half22float2(h01);
                float2 f23 = __half22float2(h23);
                l0 += f01.x + f01.y;
                l1 += f23.x + f23.y;
                int j = nt >> 1, hf = nt & 1;
                ph[j][hf * 2]     = *reinterpret_cast<uint32_t*>(&h01);
                ph[j][hf * 2 + 1] = *reinterpret_cast<uint32_t*>(&h23);
            }

            // ---- O += P V ----
#pragma unroll
            for (int j = 0; j < 4; j++) {
#pragma unroll
                for (int dg = 0; dg < 4; dg++) {
                    uint32_t addr = vhi + (uint32_t)(j * 16 + b_row) * FROWB
                                  + dg * 32 + b_koff;
                    uint32_t th[4];
                    LDSM4T(th, addr);
                    uint32_t bh0[2] = {th[0], th[2]}, bh1[2] = {th[1], th[3]};
                    MMA16816(oacc[dg * 2],     ph[j], bh0);
                    MMA16816(oacc[dg * 2 + 1], ph[j], bh1);
                }
            }
        }
    }

    l0 += __shfl_xor_sync(0xffffffffu, l0, 1);
    l0 += __shfl_xor_sync(0xffffffffu, l0, 2);
    l1 += __shfl_xor_sync(0xffffffffu, l1, 1);
    l1 += __shfl_xor_sync(0xffffffffu, l1, 2);

    float inv0 = 1.f / fmaxf(l0, 1e-37f);
    float inv1 = 1.f / fmaxf(l1, 1e-37f);
#pragma unroll
    for (int nt = 0; nt < 8; nt++) {
        int d = nt * 8 + qr;
        if (qrow0 < LSEQ) {
            size_t off = ((size_t)b * LSEQ + qrow0) * CDIM + h * HD + d;
            __half2 hv = __floats2half2_rn(oacc[nt][0] * inv0, oacc[nt][1] * inv0);
            *(uint32_t*)(g_yh + off) = *reinterpret_cast<uint32_t*>(&hv);
        }
        if (qrow1 < LSEQ) {
            size_t off = ((size_t)b * LSEQ + qrow1) * CDIM + h * HD + d;
            __half2 hv = __floats2half2_rn(oacc[nt][2] * inv1, oacc[nt][3] * inv1);
            *(uint32_t*)(g_yh + off) = *reinterpret_cast<uint32_t*>(&hv);
        }
    }
}

// ---------------------------------------------------------------------------
extern "C" void kernel_launch(void* const* d_in, const int* in_sizes, int n_in,
                              void* d_out, int out_size)
{
    const float* x  = (const float*)d_in[0];
    const float* Wq = (const float*)d_in[1];
    const float* bq = (const float*)d_in[2];
    const float* Wk = (const float*)d_in[3];
    const float* bk = (const float*)d_in[4];
    const float* Wv = (const float*)d_in[5];
    const float* bv = (const float*)d_in[6];
    const float* Wp = (const float*)d_in[7];
    const float* bp = (const float*)d_in[8];

    int B = in_sizes[0] / (LSEQ * CDIM);
    if (B < 1) B = 1;
    if (B > BMAX) B = BMAX;
    const int M = B * LSEQ;

    cudaFuncSetAttribute(gemm_qkv, cudaFuncAttributeMaxDynamicSharedMemorySize, GSMEM);
    cudaFuncSetAttribute(gemm_proj, cudaFuncAttributeMaxDynamicSharedMemorySize, GSMEM);
    cudaFuncSetAttribute(flash_attn_mma, cudaFuncAttributeMaxDynamicSharedMemorySize, FSMEM);

    int nx = M * CDIM;
    split_x<<<(nx / 4 + 255) / 256, 256>>>(x, nx);
    dim3 gw(CDIM * CDIM / 4 / 256, 1, 4);
    split_w<<<gw, 256>>>(Wq, Wk, Wv, Wp);

    dim3 g1(CDIM / 128, (M + 127) / 128, 3);
    gemm_qkv<<<g1, dim3(256), GSMEM>>>(bq, bk, bv, M);

    dim3 g2(26, B * NHEAD);
    flash_attn_mma<<<g2, dim3(128), FSMEM>>>(B);

    dim3 g3(CDIM / 128, (M + 127) / 128);
    gemm_proj<<<g3, dim3(256), GSMEM>>>(bp, (float*)d_out, M);
}